// round 3
// baseline (speedup 1.0000x reference)
#include <cuda_runtime.h>
#include <math.h>

#define N_ATOM  50000
#define M_NBR   12
#define N_ROW   600000
#define OFD     92
#define FDIM    64
#define EDIMM   41
#define NC_L    210
#define NC_H    256
#define UVS_L   420
#define UVS_H   512

// ---------------- scratch (device globals; no runtime allocation) ----------------
__device__ float  g_Y[(size_t)N_ROW * NC_H];      // pre-activations
__device__ float  g_G[(size_t)N_ROW * EDIMM];     // edge gate values
__device__ float  g_EDGE[(size_t)N_ROW * EDIMM];  // current edge features
__device__ float  g_NODE[N_ATOM * FDIM];          // current node features
__device__ float  g_AGGR[N_ATOM * FDIM];
__device__ float  g_UV[(size_t)N_ATOM * UVS_H];   // packed self/nbr partial products
__device__ float  g_WP[FDIM * UVS_H];             // packed UV weights
__device__ float  g_BP[UVS_H];                    // packed bias
__device__ float  g_EW[EDIMM * NC_H];             // packed edge-part weights
__device__ float  g_DIST[N_ROW];
__device__ double g_S[2 * NC_H];
__device__ double g_SA[2 * FDIM];
__device__ double g_SG[2 * EDIMM];
__device__ float  g_MEAN[NC_H], g_ISTD[NC_H];
__device__ float  g_MEANA[FDIM], g_ISTDA[FDIM];
__device__ float  g_MEANG[EDIMM], g_ISTDG[EDIMM];

__device__ __forceinline__ float lrelu(float x){ return x > 0.f ? x : 0.01f*x; }
__device__ __forceinline__ float sigm(float x){ return 1.f/(1.f + __expf(-x)); }
__device__ __forceinline__ float softplus(float x){ return fmaxf(x,0.f) + log1pf(__expf(-fabsf(x))); }

// ---------------- distance ----------------
__global__ void k_dist(const float* __restrict__ nbr, const float* __restrict__ pos,
                       const float* __restrict__ cells, const int* __restrict__ eidx)
{
    int r = blockIdx.x*blockDim.x + threadIdx.x;
    if (r >= N_ROW) return;
    int n = r / M_NBR;
    float o0=nbr[r*3], o1=nbr[r*3+1], o2=nbr[r*3+2];
    const float* c = cells + (size_t)n*9;
    int g = eidx[r];
    float dd = 1e-12f;
    #pragma unroll
    for (int j=0;j<3;j++){
        float off = o0*c[j] + o1*c[3+j] + o2*c[6+j];
        float d = pos[g*3+j] + off - pos[n*3+j];
        dd += d*d;
    }
    g_DIST[r] = sqrtf(dd);
}

// ---------------- embedding GEMM (small): g_NODE = node_fea @ W_emb + b_emb ----------------
__global__ void __launch_bounds__(256) k_gemm_emb(const float* __restrict__ A,
                                                  const float* __restrict__ B,
                                                  const float* __restrict__ bias,
                                                  int Nrows, int K, int Ncols)
{
    __shared__ float As[64*32];
    __shared__ float Bs[32*128];
    int tid = threadIdx.x;
    int colT = tid & 31, rowT = tid >> 5;
    int r0 = blockIdx.x*64, c0 = 0;
    float acc[8][4];
    #pragma unroll
    for (int ri=0;ri<8;ri++)
        #pragma unroll
        for (int ci=0;ci<4;ci++) acc[ri][ci]=0.f;

    for (int k0=0;k0<K;k0+=32){
        for (int i=tid;i<64*32;i+=256){
            int rr=i>>5, kk=i&31; int gr=r0+rr, gk=k0+kk;
            As[i] = (gr<Nrows && gk<K)? A[(size_t)gr*K+gk] : 0.f;
        }
        for (int i=tid;i<32*128;i+=256){
            int kk=i>>7, jj=i&127; int gk=k0+kk, gj=c0+jj;
            Bs[i] = (gk<K && gj<Ncols)? B[(size_t)gk*Ncols+gj] : 0.f;
        }
        __syncthreads();
        #pragma unroll 4
        for (int kk=0;kk<32;kk++){
            float a[8];
            #pragma unroll
            for (int ri=0;ri<8;ri++) a[ri]=As[(rowT+8*ri)*32+kk];
            #pragma unroll
            for (int ci=0;ci<4;ci++){
                float b=Bs[kk*128 + colT + 32*ci];
                #pragma unroll
                for (int ri=0;ri<8;ri++) acc[ri][ci] = fmaf(a[ri], b, acc[ri][ci]);
            }
        }
        __syncthreads();
    }
    #pragma unroll
    for (int ri=0;ri<8;ri++){
        int gr=r0+rowT+8*ri;
        if (gr >= Nrows) continue;
        #pragma unroll
        for (int ci=0;ci<4;ci++){
            int gj=c0+colT+32*ci;
            if (gj < Ncols) g_NODE[(size_t)gr*Ncols+gj] = acc[ri][ci] + bias[gj];
        }
    }
}

// ---------------- UV GEMM: g_UV = g_NODE(50000x64) @ g_WP(64 x Ncols) + g_BP ----------------
__global__ void __launch_bounds__(256) k_gemm_uv(int Ncols)
{
    __shared__ float As[16][128];   // [k][m]  (transposed A tile)
    __shared__ float Bs[16][128];   // [k][n]
    int tid = threadIdx.x;
    int tx = tid & 15, ty = tid >> 4;
    int r0 = blockIdx.x*128, c0 = blockIdx.y*128;
    float acc[8][8];
    #pragma unroll
    for (int i=0;i<8;i++)
        #pragma unroll
        for (int j=0;j<8;j++) acc[i][j]=0.f;

    for (int k0=0;k0<FDIM;k0+=16){
        #pragma unroll
        for (int h=0;h<2;h++){
            int arow = (tid>>2) + h*64;
            int acol = (tid&3)*4;
            float4 v = make_float4(0.f,0.f,0.f,0.f);
            int gr = r0 + arow;
            if (gr < N_ATOM) v = *(const float4*)&g_NODE[(size_t)gr*FDIM + k0 + acol];
            As[acol+0][arow]=v.x; As[acol+1][arow]=v.y; As[acol+2][arow]=v.z; As[acol+3][arow]=v.w;
        }
        #pragma unroll
        for (int h=0;h<2;h++){
            int brow = (tid>>5) + h*8;
            int bcol = (tid&31)*4;
            float4 v = make_float4(0.f,0.f,0.f,0.f);
            if (c0 + bcol < Ncols) v = *(const float4*)&g_WP[(size_t)(k0+brow)*Ncols + c0 + bcol];
            *(float4*)&Bs[brow][bcol] = v;
        }
        __syncthreads();
        #pragma unroll
        for (int kk=0;kk<16;kk++){
            float a[8], b[8];
            *(float4*)&a[0] = *(const float4*)&As[kk][ty*8];
            *(float4*)&a[4] = *(const float4*)&As[kk][ty*8+4];
            *(float4*)&b[0] = *(const float4*)&Bs[kk][tx*8];
            *(float4*)&b[4] = *(const float4*)&Bs[kk][tx*8+4];
            #pragma unroll
            for (int i=0;i<8;i++)
                #pragma unroll
                for (int j=0;j<8;j++) acc[i][j] = fmaf(a[i], b[j], acc[i][j]);
        }
        __syncthreads();
    }
    #pragma unroll
    for (int ri=0;ri<8;ri++){
        int gr = r0 + ty*8 + ri;
        if (gr >= N_ATOM) continue;
        #pragma unroll
        for (int cj=0;cj<2;cj++){
            int gj = c0 + tx*8 + cj*4;
            if (gj < Ncols){
                float4 bv = *(const float4*)&g_BP[gj];
                float4 o;
                o.x = acc[ri][cj*4+0] + bv.x;
                o.y = acc[ri][cj*4+1] + bv.y;
                o.z = acc[ri][cj*4+2] + bv.z;
                o.w = acc[ri][cj*4+3] + bv.w;
                *(float4*)&g_UV[(size_t)gr*Ncols + gj] = o;
            }
        }
    }
}

// ---------------- weight packing ----------------
__global__ void k_pack_layer(const float* __restrict__ Wn, const float* __restrict__ bn,
                             const float* __restrict__ We, const float* __restrict__ be)
{
    int stride = gridDim.x*blockDim.x;
    int t0 = blockIdx.x*blockDim.x + threadIdx.x;
    for (int idx=t0; idx<FDIM*UVS_L; idx+=stride){
        int k = idx / UVS_L, j = idx % UVS_L;
        float v;
        if (j<128)       v = Wn[k*128 + j];
        else if (j<256)  v = Wn[(64+k)*128 + (j-128)];
        else if (j<338)  v = We[k*82 + (j-256)];
        else             v = We[(64+k)*82 + (j-338)];
        g_WP[idx] = v;
    }
    for (int j=t0;j<UVS_L;j+=stride){
        float v = 0.f;
        if (j<128) v = bn[j];
        else if (j>=256 && j<338) v = be[j-256];
        g_BP[j]=v;
    }
    for (int idx=t0;idx<EDIMM*NC_L;idx+=stride){
        int k=idx/NC_L, j=idx%NC_L;
        g_EW[idx] = (j<128)? Wn[(128+k)*128 + j] : We[(128+k)*82 + (j-128)];
    }
}

__global__ void k_pack_head(const float* __restrict__ Wd, const float* __restrict__ bd,
                            const float* __restrict__ Wc, const float* __restrict__ bc)
{
    int stride = gridDim.x*blockDim.x;
    int t0 = blockIdx.x*blockDim.x + threadIdx.x;
    for (int idx=t0; idx<FDIM*UVS_H; idx+=stride){
        int k = idx / UVS_H, j = idx % UVS_H;
        float v;
        if (j<128)       v = Wd[k*128 + j];
        else if (j<256)  v = Wd[(64+k)*128 + (j-128)];
        else if (j<384)  v = Wc[k*128 + (j-256)];
        else             v = Wc[(64+k)*128 + (j-384)];
        g_WP[idx] = v;
    }
    for (int j=t0;j<UVS_H;j+=stride){
        float v = 0.f;
        if (j<128) v = bd[j];
        else if (j>=256 && j<384) v = bc[j-256];
        g_BP[j]=v;
    }
    for (int idx=t0;idx<EDIMM*NC_H;idx+=stride){
        int k=idx/NC_H, j=idx%NC_H;
        g_EW[idx] = (j<128)? Wd[(128+k)*128 + j] : Wc[(128+k)*128 + (j-128)];
    }
}

__global__ void k_zero_stats()
{
    int t = blockIdx.x*blockDim.x + threadIdx.x;
    if (t < 2*NC_H)  g_S[t]=0.0;
    if (t < 2*FDIM)  g_SA[t]=0.0;
    if (t < 2*EDIMM) g_SG[t]=0.0;
}

// ---------------- pass1: Y = edge@EW + U[n] + V[g]; accumulate channel stats ----------------
// Tile: 8*RPT rows per block; 8 warps; each thread RPT rows x CPT cols (stride 32).
template<int NC, int CPT, int RPT>
__global__ void __launch_bounds__(256,2) k_pass1(const float* __restrict__ Ein, int useG,
                                                 const int* __restrict__ eidx, int uvS)
{
    __shared__ float sEW[EDIMM*NC];
    __shared__ float sE[8*RPT*EDIMM];
    const float* E = useG ? g_EDGE : Ein;
    const int tid = threadIdx.x;
    const int colT = tid & 31, rowT = tid >> 5;
    const int TR = 8*RPT;
    for (int i=tid; i<EDIMM*NC; i+=256) sEW[i] = g_EW[i];
    float s1[CPT], s2[CPT];
    #pragma unroll
    for (int ci=0;ci<CPT;ci++){ s1[ci]=0.f; s2[ci]=0.f; }
    const int nTiles = N_ROW / TR;
    for (int t = blockIdx.x; t < nTiles; t += gridDim.x){
        int r0 = t*TR;
        __syncthreads();
        for (int i=tid;i<TR*EDIMM;i+=256) sE[i] = E[(size_t)r0*EDIMM + i];
        __syncthreads();
        float acc[RPT][CPT];
        #pragma unroll
        for (int ri=0;ri<RPT;ri++)
            #pragma unroll
            for (int ci=0;ci<CPT;ci++) acc[ri][ci]=0.f;
        const float* pE = sE + rowT*RPT*EDIMM;
        const float* pW = sEW + colT;
        #pragma unroll 2
        for (int k=0;k<EDIMM;k++){
            float ev[RPT];
            #pragma unroll
            for (int ri=0;ri<RPT;ri++) ev[ri] = pE[ri*EDIMM];
            #pragma unroll
            for (int ci=0;ci<CPT;ci++){
                float w = pW[32*ci];
                #pragma unroll
                for (int ri=0;ri<RPT;ri++) acc[ri][ci] = fmaf(ev[ri], w, acc[ri][ci]);
            }
            pE += 1; pW += NC;
        }
        #pragma unroll
        for (int ri=0;ri<RPT;ri++){
            int row = r0 + rowT*RPT + ri;
            int n  = row / M_NBR;
            int gg = __ldg(&eidx[row]);
            const float* Un = g_UV + (size_t)n*uvS;
            const float* Vg = g_UV + (size_t)gg*uvS;
            float* yp = g_Y + (size_t)row*NC;
            #pragma unroll
            for (int ci=0;ci<CPT;ci++){
                int j = colT + 32*ci;
                if (NC == 256 || j < NC){
                    int uc = (j<128)? j       : j+128;
                    int vc = (j<128)? (j+128) : j+NC;
                    float y = acc[ri][ci] + Un[uc] + Vg[vc];
                    yp[j] = y;
                    s1[ci] += y;
                    s2[ci] += y*y;
                }
            }
        }
    }
    __syncthreads();
    float* red = sE; // >= 512 floats
    #pragma unroll 1
    for (int ci=0;ci<CPT;ci++){
        red[tid] = s1[ci];
        red[256+tid] = s2[ci];
        __syncthreads();
        if (tid < 32){
            float a=0.f, b=0.f;
            #pragma unroll
            for (int w=0;w<8;w++){ a += red[w*32+tid]; b += red[256+w*32+tid]; }
            int j = tid + 32*ci;
            if (j < NC){
                atomicAdd(&g_S[j],    (double)a);
                atomicAdd(&g_S[NC+j], (double)b);
            }
        }
        __syncthreads();
    }
}

// ---------------- finalize stats: mean / inv_std ----------------
__global__ void k_finalize(int mode, int C, double invCnt)
{
    int t = threadIdx.x + blockIdx.x*blockDim.x;
    if (t >= C) return;
    const double* S; float* mean; float* istd;
    if (mode==0){ S=g_S;  mean=g_MEAN;  istd=g_ISTD;  }
    else if (mode==1){ S=g_SA; mean=g_MEANA; istd=g_ISTDA; }
    else { S=g_SG; mean=g_MEANG; istd=g_ISTDG; }
    double m = S[t]*invCnt;
    double v = S[C+t]*invCnt - m*m;
    mean[t] = (float)m;
    istd[t] = rsqrtf((float)v + 1e-5f);
}

// ---------------- pass2 (layer): BN + gates, M-reduction, write aggr & g, next-BN stats ----------------
__global__ void __launch_bounds__(128) k_pass2_layer()
{
    int t = threadIdx.x;
    bool isNode = t < 64;
    bool isEdge = (t >= 64 && t < 105);
    float m1=0.f,i1=0.f,m2=0.f,i2=0.f;
    int c = 0;
    if (isNode){ c=t;    m1=g_MEAN[c];     i1=g_ISTD[c];     m2=g_MEAN[64+c];  i2=g_ISTD[64+c]; }
    else if (isEdge){ c=t-64; m1=g_MEAN[128+c]; i1=g_ISTD[128+c]; m2=g_MEAN[169+c]; i2=g_ISTD[169+c]; }
    float st1=0.f, st2=0.f;
    for (int n = blockIdx.x; n < N_ATOM; n += gridDim.x){
        if (isNode){
            float a = 0.f;
            #pragma unroll
            for (int m=0;m<M_NBR;m++){
                size_t row = (size_t)(n*M_NBR+m);
                float y1 = (g_Y[row*NC_L + c]      - m1)*i1;
                float y2 = (g_Y[row*NC_L + 64 + c] - m2)*i2;
                a += sigm(y1)*lrelu(y2);
            }
            g_AGGR[n*64 + c] = a;
            st1 += a; st2 += a*a;
        } else if (isEdge){
            #pragma unroll
            for (int m=0;m<M_NBR;m++){
                size_t row = (size_t)(n*M_NBR+m);
                float y1 = (g_Y[row*NC_L + 128 + c] - m1)*i1;
                float y2 = (g_Y[row*NC_L + 169 + c] - m2)*i2;
                float gv = sigm(y1)*lrelu(y2);
                g_G[row*EDIMM + c] = gv;
                st1 += gv; st2 += gv*gv;
            }
        }
    }
    if (isNode){ atomicAdd(&g_SA[c], (double)st1); atomicAdd(&g_SA[64+c], (double)st2); }
    else if (isEdge){ atomicAdd(&g_SG[c], (double)st1); atomicAdd(&g_SG[41+c], (double)st2); }
}

__global__ void k_node_update()
{
    int idx = blockIdx.x*blockDim.x + threadIdx.x;
    if (idx >= N_ATOM*FDIM) return;
    int c = idx & 63;
    float v = g_NODE[idx] + (g_AGGR[idx] - g_MEANA[c]) * g_ISTDA[c];
    g_NODE[idx] = lrelu(v);
}

__global__ void k_edge_update(const float* __restrict__ Ein, int useG)
{
    size_t idx = (size_t)blockIdx.x*blockDim.x + threadIdx.x;
    if (idx >= (size_t)N_ROW*EDIMM) return;
    int c = (int)(idx % EDIMM);
    float e = useG ? g_EDGE[idx] : Ein[idx];
    float v = e + (g_G[idx] - g_MEANG[c]) * g_ISTDG[c];
    g_EDGE[idx] = lrelu(v);
}

// ---------------- pass2 (head): BN + softplus + channel means -> output ----------------
__global__ void __launch_bounds__(256) k_pass2_head(float* __restrict__ out)
{
    int warp = threadIdx.x >> 5, lane = threadIdx.x & 31;
    size_t r = (size_t)blockIdx.x*8 + warp;
    if (r >= N_ROW) return;
    float dist = g_DIST[r];
    float bd = 0.f, bc = 0.f;
    const float* y = g_Y + r*NC_H;
    #pragma unroll
    for (int i=0;i<8;i++){
        int cidx = lane + 32*i;
        float v = (y[cidx] - g_MEAN[cidx]) * g_ISTD[cidx];
        if (i < 4) bd += softplus(v + dist);
        else       bc += softplus(v);
    }
    #pragma unroll
    for (int o=16;o>0;o>>=1){
        bd += __shfl_down_sync(0xffffffffu, bd, o);
        bc += __shfl_down_sync(0xffffffffu, bc, o);
    }
    if (lane==0){
        out[r*2]   = bd * (1.f/128.f);
        out[r*2+1] = bc * (1.f/128.f) * (1.f/(float)N_ATOM);
    }
}

// ---------------- host orchestration ----------------
extern "C" void kernel_launch(void* const* d_in, const int* in_sizes, int n_in,
                              void* d_out, int out_size)
{
    const float* node_fea = (const float*)d_in[0];
    const float* edge_fea = (const float*)d_in[1];
    const float* nbr_off  = (const float*)d_in[2];
    const float* atom_pos = (const float*)d_in[3];
    const float* cells    = (const float*)d_in[4];
    const int*   eidx     = (const int*)  d_in[5];
    const float* W_emb = (const float*)d_in[6];
    const float* b_emb = (const float*)d_in[7];
    const float* W_pn  = (const float*)d_in[8];
    const float* b_pn  = (const float*)d_in[9];
    const float* W_pe  = (const float*)d_in[10];
    const float* b_pe  = (const float*)d_in[11];
    const float* W_d   = (const float*)d_in[12];
    const float* b_d   = (const float*)d_in[13];
    const float* W_c   = (const float*)d_in[14];
    const float* b_c   = (const float*)d_in[15];
    float* out = (float*)d_out;

    k_dist<<<(N_ROW+255)/256, 256>>>(nbr_off, atom_pos, cells, eidx);
    k_gemm_emb<<<(N_ATOM+63)/64, 256>>>(node_fea, W_emb, b_emb, N_ATOM, OFD, FDIM);

    for (int l=0;l<3;l++){
        int useG = (l>0) ? 1 : 0;
        k_pack_layer<<<64,256>>>(W_pn + (size_t)l*169*128, b_pn + l*128,
                                 W_pe + (size_t)l*169*82,  b_pe + l*82);
        k_gemm_uv<<<dim3((N_ATOM+127)/128, (UVS_L+127)/128), 256>>>(UVS_L);
        k_zero_stats<<<2,256>>>();
        k_pass1<NC_L,7,8><<<1184,256>>>(edge_fea, useG, eidx, UVS_L);
        k_finalize<<<1,256>>>(0, NC_L, 1.0/(double)N_ROW);
        k_pass2_layer<<<2368,128>>>();
        k_finalize<<<1,256>>>(1, FDIM,  1.0/(double)N_ATOM);
        k_finalize<<<1,256>>>(2, EDIMM, 1.0/(double)N_ROW);
        k_node_update<<<(N_ATOM*FDIM+255)/256,256>>>();
        k_edge_update<<<(int)(((size_t)N_ROW*EDIMM+255)/256),256>>>(edge_fea, useG);
    }

    k_pack_head<<<64,256>>>(W_d, b_d, W_c, b_c);
    k_gemm_uv<<<dim3((N_ATOM+127)/128, (UVS_H+127)/128), 256>>>(UVS_H);
    k_zero_stats<<<2,256>>>();
    k_pass1<NC_H,8,5><<<1184,256>>>(nullptr, 1, eidx, UVS_H);
    k_finalize<<<1,256>>>(0, NC_H, 1.0/(double)N_ROW);
    k_pass2_head<<<(int)((N_ROW+7)/8), 256>>>(out);
}

// round 5
// speedup vs baseline: 1.0057x; 1.0057x over previous
#include <cuda_runtime.h>
#include <math.h>

#define N_ATOM  50000
#define M_NBR   12
#define N_ROW   600000
#define OFD     92
#define FDIM    64
#define EDIMM   41
#define NC_L    210
#define NC_H    256
#define UVS_L   420
#define UVS_H   512

// ---------------- scratch (device globals; no runtime allocation) ----------------
__device__ __align__(16) float  g_Y[(size_t)N_ROW * NC_H];
__device__ __align__(16) float  g_G[(size_t)N_ROW * EDIMM];
__device__ __align__(16) float  g_EDGE[(size_t)N_ROW * EDIMM];
__device__ __align__(16) float  g_NODE[N_ATOM * FDIM];
__device__ __align__(16) float  g_AGGR[N_ATOM * FDIM];
__device__ __align__(16) float  g_UV[(size_t)N_ATOM * UVS_H];
__device__ __align__(16) float  g_WP[FDIM * UVS_H];
__device__ __align__(16) float  g_BP[UVS_H];
__device__ __align__(16) float  g_EW[EDIMM * NC_H];
__device__ __align__(16) float  g_DIST[N_ROW];
__device__ double g_S[2 * NC_H];
__device__ double g_SA[2 * FDIM];
__device__ double g_SG[2 * EDIMM];
__device__ float  g_MEAN[NC_H], g_ISTD[NC_H];
__device__ float  g_MEANA[FDIM], g_ISTDA[FDIM];
__device__ float  g_MEANG[EDIMM], g_ISTDG[EDIMM];

__device__ __forceinline__ float lrelu(float x){ return x > 0.f ? x : 0.01f*x; }
__device__ __forceinline__ float sigm(float x){ return 1.f/(1.f + __expf(-x)); }
__device__ __forceinline__ float softplus(float x){ return fmaxf(x,0.f) + log1pf(__expf(-fabsf(x))); }

// ---------------- distance ----------------
__global__ void k_dist(const float* __restrict__ nbr, const float* __restrict__ pos,
                       const float* __restrict__ cells, const int* __restrict__ eidx)
{
    int r = blockIdx.x*blockDim.x + threadIdx.x;
    if (r >= N_ROW) return;
    int n = r / M_NBR;
    float o0=nbr[r*3], o1=nbr[r*3+1], o2=nbr[r*3+2];
    const float* c = cells + (size_t)n*9;
    int g = eidx[r];
    float dd = 1e-12f;
    #pragma unroll
    for (int j=0;j<3;j++){
        float off = o0*c[j] + o1*c[3+j] + o2*c[6+j];
        float d = pos[g*3+j] + off - pos[n*3+j];
        dd += d*d;
    }
    g_DIST[r] = sqrtf(dd);
}

// ---------------- embedding GEMM: g_NODE = node_fea @ W_emb + b_emb ----------------
__global__ void __launch_bounds__(256) k_gemm_emb(const float* __restrict__ A,
                                                  const float* __restrict__ B,
                                                  const float* __restrict__ bias,
                                                  int Nrows, int K, int Ncols)
{
    __shared__ float As[64*32];
    __shared__ float Bs[32*128];
    int tid = threadIdx.x;
    int colT = tid & 31, rowT = tid >> 5;
    int r0 = blockIdx.x*64;
    float acc[8][4];
    #pragma unroll
    for (int ri=0;ri<8;ri++)
        #pragma unroll
        for (int ci=0;ci<4;ci++) acc[ri][ci]=0.f;

    for (int k0=0;k0<K;k0+=32){
        for (int i=tid;i<64*32;i+=256){
            int rr=i>>5, kk=i&31; int gr=r0+rr, gk=k0+kk;
            As[i] = (gr<Nrows && gk<K)? A[(size_t)gr*K+gk] : 0.f;
        }
        for (int i=tid;i<32*128;i+=256){
            int kk=i>>7, jj=i&127; int gk=k0+kk;
            Bs[i] = (gk<K && jj<Ncols)? B[(size_t)gk*Ncols+jj] : 0.f;
        }
        __syncthreads();
        #pragma unroll 4
        for (int kk=0;kk<32;kk++){
            float a[8];
            #pragma unroll
            for (int ri=0;ri<8;ri++) a[ri]=As[(rowT+8*ri)*32+kk];
            #pragma unroll
            for (int ci=0;ci<4;ci++){
                float b=Bs[kk*128 + colT + 32*ci];
                #pragma unroll
                for (int ri=0;ri<8;ri++) acc[ri][ci] = fmaf(a[ri], b, acc[ri][ci]);
            }
        }
        __syncthreads();
    }
    #pragma unroll
    for (int ri=0;ri<8;ri++){
        int gr=r0+rowT+8*ri;
        if (gr >= Nrows) continue;
        #pragma unroll
        for (int ci=0;ci<4;ci++){
            int gj=colT+32*ci;
            if (gj < Ncols) g_NODE[(size_t)gr*Ncols+gj] = acc[ri][ci] + bias[gj];
        }
    }
}

// ---------------- UV GEMM: g_UV = g_NODE(50000x64) @ g_WP(64 x Ncols) + g_BP ----------------
__global__ void __launch_bounds__(256) k_gemm_uv(int Ncols)
{
    __shared__ __align__(16) float As[16][128];
    __shared__ __align__(16) float Bs[16][128];
    int tid = threadIdx.x;
    int tx = tid & 15, ty = tid >> 4;
    int r0 = blockIdx.x*128, c0 = blockIdx.y*128;
    float acc[8][8];
    #pragma unroll
    for (int i=0;i<8;i++)
        #pragma unroll
        for (int j=0;j<8;j++) acc[i][j]=0.f;

    for (int k0=0;k0<FDIM;k0+=16){
        #pragma unroll
        for (int h=0;h<2;h++){
            int arow = (tid>>2) + h*64;
            int acol = (tid&3)*4;
            float4 v = make_float4(0.f,0.f,0.f,0.f);
            int gr = r0 + arow;
            if (gr < N_ATOM) v = *(const float4*)&g_NODE[(size_t)gr*FDIM + k0 + acol];
            As[acol+0][arow]=v.x; As[acol+1][arow]=v.y; As[acol+2][arow]=v.z; As[acol+3][arow]=v.w;
        }
        #pragma unroll
        for (int h=0;h<2;h++){
            int brow = (tid>>5) + h*8;
            int bcol = (tid&31)*4;
            float4 v = make_float4(0.f,0.f,0.f,0.f);
            if (c0 + bcol < Ncols) v = *(const float4*)&g_WP[(size_t)(k0+brow)*Ncols + c0 + bcol];
            *(float4*)&Bs[brow][bcol] = v;
        }
        __syncthreads();
        #pragma unroll
        for (int kk=0;kk<16;kk++){
            float a[8], b[8];
            *(float4*)&a[0] = *(const float4*)&As[kk][ty*8];
            *(float4*)&a[4] = *(const float4*)&As[kk][ty*8+4];
            *(float4*)&b[0] = *(const float4*)&Bs[kk][tx*8];
            *(float4*)&b[4] = *(const float4*)&Bs[kk][tx*8+4];
            #pragma unroll
            for (int i=0;i<8;i++)
                #pragma unroll
                for (int j=0;j<8;j++) acc[i][j] = fmaf(a[i], b[j], acc[i][j]);
        }
        __syncthreads();
    }
    #pragma unroll
    for (int ri=0;ri<8;ri++){
        int gr = r0 + ty*8 + ri;
        if (gr >= N_ATOM) continue;
        #pragma unroll
        for (int cj=0;cj<2;cj++){
            int gj = c0 + tx*8 + cj*4;
            if (gj < Ncols){
                float4 bv = *(const float4*)&g_BP[gj];
                float4 o;
                o.x = acc[ri][cj*4+0] + bv.x;
                o.y = acc[ri][cj*4+1] + bv.y;
                o.z = acc[ri][cj*4+2] + bv.z;
                o.w = acc[ri][cj*4+3] + bv.w;
                *(float4*)&g_UV[(size_t)gr*Ncols + gj] = o;
            }
        }
    }
}

// ---------------- weight packing (+ stat zeroing) ----------------
__global__ void k_pack_layer(const float* __restrict__ Wn, const float* __restrict__ bn,
                             const float* __restrict__ We, const float* __restrict__ be)
{
    int stride = gridDim.x*blockDim.x;
    int t0 = blockIdx.x*blockDim.x + threadIdx.x;
    for (int idx=t0; idx<FDIM*UVS_L; idx+=stride){
        int k = idx / UVS_L, j = idx % UVS_L;
        float v;
        if (j<128)       v = Wn[k*128 + j];
        else if (j<256)  v = Wn[(64+k)*128 + (j-128)];
        else if (j<338)  v = We[k*82 + (j-256)];
        else             v = We[(64+k)*82 + (j-338)];
        g_WP[idx] = v;
    }
    for (int j=t0;j<UVS_L;j+=stride){
        float v = 0.f;
        if (j<128) v = bn[j];
        else if (j>=256 && j<338) v = be[j-256];
        g_BP[j]=v;
    }
    for (int idx=t0;idx<EDIMM*NC_L;idx+=stride){
        int k=idx/NC_L, j=idx%NC_L;
        g_EW[idx] = (j<128)? Wn[(128+k)*128 + j] : We[(128+k)*82 + (j-128)];
    }
    if (t0 < 2*NC_H)  g_S[t0]=0.0;
    if (t0 < 2*FDIM)  g_SA[t0]=0.0;
    if (t0 < 2*EDIMM) g_SG[t0]=0.0;
}

__global__ void k_pack_head(const float* __restrict__ Wd, const float* __restrict__ bd,
                            const float* __restrict__ Wc, const float* __restrict__ bc)
{
    int stride = gridDim.x*blockDim.x;
    int t0 = blockIdx.x*blockDim.x + threadIdx.x;
    for (int idx=t0; idx<FDIM*UVS_H; idx+=stride){
        int k = idx / UVS_H, j = idx % UVS_H;
        float v;
        if (j<128)       v = Wd[k*128 + j];
        else if (j<256)  v = Wd[(64+k)*128 + (j-128)];
        else if (j<384)  v = Wc[k*128 + (j-256)];
        else             v = Wc[(64+k)*128 + (j-384)];
        g_WP[idx] = v;
    }
    for (int j=t0;j<UVS_H;j+=stride){
        float v = 0.f;
        if (j<128) v = bd[j];
        else if (j>=256 && j<384) v = bc[j-256];
        g_BP[j]=v;
    }
    for (int idx=t0;idx<EDIMM*NC_H;idx+=stride){
        int k=idx/NC_H, j=idx%NC_H;
        g_EW[idx] = (j<128)? Wd[(128+k)*128 + j] : Wc[(128+k)*128 + (j-128)];
    }
    if (t0 < 2*NC_H) g_S[t0]=0.0;
}

// ---------------- pass1 core (shared by all variants) ----------------
// EDGE_SRC: 0 = Ein arg, 1 = g_EDGE global.
// MODE:     0 = raw edge, 1 = fused edge update e' = lrelu(e + (G-mean)*istd).
// WRITE_E:  store e' back to g_EDGE.
template<int NC, int CPT, int EDGE_SRC, int MODE, int WRITE_E>
__device__ __forceinline__ void pass1_body(const float* __restrict__ Ein,
                                           const int* __restrict__ eidx, int uvS)
{
    const int RPT = 6;
    const int TR  = 48;
    const int TF4 = TR*EDIMM/4;   // 492
    __shared__ __align__(16) float sE[TR*EDIMM];
    __shared__ float sEW[EDIMM*NC];
    __shared__ float sMg[EDIMM], sIg[EDIMM];
    const int tid = threadIdx.x;
    const int colT = tid & 31, rowT = tid >> 5;
    for (int i=tid; i<EDIMM*NC; i+=256) sEW[i] = g_EW[i];
    if (MODE==1 && tid < EDIMM){ sMg[tid] = g_MEANG[tid]; sIg[tid] = g_ISTDG[tid]; }
    float s1[CPT], s2[CPT];
    #pragma unroll
    for (int ci=0;ci<CPT;ci++){ s1[ci]=0.f; s2[ci]=0.f; }
    const int nTiles = N_ROW / TR;
    for (int t = blockIdx.x; t < nTiles; t += gridDim.x){
        int r0 = t*TR;
        size_t base = (size_t)r0*EDIMM;
        __syncthreads();
        const float* Eptr = (EDGE_SRC==0) ? (Ein + base) : (g_EDGE + base);
        if (MODE==0){
            const float4* src = (const float4*)Eptr;
            #pragma unroll 2
            for (int i4=tid; i4<TF4; i4+=256)
                *(float4*)&sE[i4*4] = src[i4];
        } else {
            const float4* src = (const float4*)Eptr;
            const float4* gsr = (const float4*)(g_G + base);
            #pragma unroll 2
            for (int i4=tid; i4<TF4; i4+=256){
                float4 e = src[i4];
                float4 g = gsr[i4];
                int c0 = (i4*4) % EDIMM;
                int c1 = c0+1 >= EDIMM ? c0+1-EDIMM : c0+1;
                int c2 = c0+2 >= EDIMM ? c0+2-EDIMM : c0+2;
                int c3 = c0+3 >= EDIMM ? c0+3-EDIMM : c0+3;
                float4 o;
                o.x = lrelu(e.x + (g.x - sMg[c0])*sIg[c0]);
                o.y = lrelu(e.y + (g.y - sMg[c1])*sIg[c1]);
                o.z = lrelu(e.z + (g.z - sMg[c2])*sIg[c2]);
                o.w = lrelu(e.w + (g.w - sMg[c3])*sIg[c3]);
                *(float4*)&sE[i4*4] = o;
                if (WRITE_E) *(float4*)(g_EDGE + base + (size_t)i4*4) = o;
            }
        }
        __syncthreads();
        float acc[RPT][CPT];
        #pragma unroll
        for (int ri=0;ri<RPT;ri++)
            #pragma unroll
            for (int ci=0;ci<CPT;ci++) acc[ri][ci]=0.f;
        const float* pE = sE + rowT*RPT*EDIMM;
        const float* pW = sEW + colT;
        #pragma unroll 2
        for (int k=0;k<EDIMM;k++){
            float ev[RPT];
            #pragma unroll
            for (int ri=0;ri<RPT;ri++) ev[ri] = pE[ri*EDIMM];
            #pragma unroll
            for (int ci=0;ci<CPT;ci++){
                float w = pW[32*ci];
                #pragma unroll
                for (int ri=0;ri<RPT;ri++) acc[ri][ci] = fmaf(ev[ri], w, acc[ri][ci]);
            }
            pE += 1; pW += NC;
        }
        #pragma unroll
        for (int ri=0;ri<RPT;ri++){
            int row = r0 + rowT*RPT + ri;
            int n  = row / M_NBR;
            int gg = __ldg(&eidx[row]);
            const float* Un = g_UV + (size_t)n*uvS;
            const float* Vg = g_UV + (size_t)gg*uvS;
            float* yp = g_Y + (size_t)row*NC;
            #pragma unroll
            for (int ci=0;ci<CPT;ci++){
                int j = colT + 32*ci;
                if (NC == 256 || j < NC){
                    int uc = (j<128)? j       : j+128;
                    int vc = (j<128)? (j+128) : j+NC;
                    float y = acc[ri][ci] + Un[uc] + Vg[vc];
                    yp[j] = y;
                    s1[ci] += y;
                    s2[ci] += y*y;
                }
            }
        }
    }
    __syncthreads();
    float* red = sE;
    #pragma unroll 1
    for (int ci=0;ci<CPT;ci++){
        red[tid] = s1[ci];
        red[256+tid] = s2[ci];
        __syncthreads();
        if (tid < 32){
            float a=0.f, b=0.f;
            #pragma unroll
            for (int w=0;w<8;w++){ a += red[w*32+tid]; b += red[256+w*32+tid]; }
            int j = tid + 32*ci;
            if (j < NC){
                atomicAdd(&g_S[j],    (double)a);
                atomicAdd(&g_S[NC+j], (double)b);
            }
        }
        __syncthreads();
    }
}

__global__ void __launch_bounds__(256,2) k_pass1_l0(const float* __restrict__ Ein,
                                                    const int* __restrict__ eidx)
{ pass1_body<NC_L,7,0,0,0>(Ein, eidx, UVS_L); }

__global__ void __launch_bounds__(256,2) k_pass1_l1(const float* __restrict__ Ein,
                                                    const int* __restrict__ eidx)
{ pass1_body<NC_L,7,0,1,1>(Ein, eidx, UVS_L); }

__global__ void __launch_bounds__(256,2) k_pass1_l2(const int* __restrict__ eidx)
{ pass1_body<NC_L,7,1,1,1>(nullptr, eidx, UVS_L); }

__global__ void __launch_bounds__(256,2) k_pass1_hd(const int* __restrict__ eidx)
{ pass1_body<NC_H,8,1,1,0>(nullptr, eidx, UVS_H); }

// ---------------- finalize stats ----------------
__global__ void k_finalize0(int C, double invCnt)
{
    int t = threadIdx.x + blockIdx.x*blockDim.x;
    if (t >= C) return;
    double m = g_S[t]*invCnt;
    double v = g_S[C+t]*invCnt - m*m;
    g_MEAN[t] = (float)m;
    g_ISTD[t] = rsqrtf((float)v + 1e-5f);
}

__global__ void k_finalize12()
{
    int t = threadIdx.x;
    if (t < FDIM){
        double m = g_SA[t] * (1.0/(double)N_ATOM);
        double v = g_SA[FDIM+t] * (1.0/(double)N_ATOM) - m*m;
        g_MEANA[t] = (float)m;
        g_ISTDA[t] = rsqrtf((float)v + 1e-5f);
    } else if (t >= 64 && t < 64+EDIMM){
        int c = t-64;
        double m = g_SG[c] * (1.0/(double)N_ROW);
        double v = g_SG[EDIMM+c] * (1.0/(double)N_ROW) - m*m;
        g_MEANG[c] = (float)m;
        g_ISTDG[c] = rsqrtf((float)v + 1e-5f);
    }
}

// ---------------- pass2 (layer) ----------------
__global__ void __launch_bounds__(128) k_pass2_layer()
{
    int t = threadIdx.x;
    bool isNode = t < 64;
    bool isEdge = (t >= 64 && t < 105);
    float m1=0.f,i1=0.f,m2=0.f,i2=0.f;
    int c = 0;
    if (isNode){ c=t;    m1=g_MEAN[c];     i1=g_ISTD[c];     m2=g_MEAN[64+c];  i2=g_ISTD[64+c]; }
    else if (isEdge){ c=t-64; m1=g_MEAN[128+c]; i1=g_ISTD[128+c]; m2=g_MEAN[169+c]; i2=g_ISTD[169+c]; }
    float st1=0.f, st2=0.f;
    for (int n = blockIdx.x; n < N_ATOM; n += gridDim.x){
        if (isNode){
            float a = 0.f;
            #pragma unroll
            for (int m=0;m<M_NBR;m++){
                size_t row = (size_t)(n*M_NBR+m);
                float y1 = (g_Y[row*NC_L + c]      - m1)*i1;
                float y2 = (g_Y[row*NC_L + 64 + c] - m2)*i2;
                a += sigm(y1)*lrelu(y2);
            }
            g_AGGR[n*64 + c] = a;
            st1 += a; st2 += a*a;
        } else if (isEdge){
            #pragma unroll
            for (int m=0;m<M_NBR;m++){
                size_t row = (size_t)(n*M_NBR+m);
                float y1 = (g_Y[row*NC_L + 128 + c] - m1)*i1;
                float y2 = (g_Y[row*NC_L + 169 + c] - m2)*i2;
                float gv = sigm(y1)*lrelu(y2);
                g_G[row*EDIMM + c] = gv;
                st1 += gv; st2 += gv*gv;
            }
        }
    }
    if (isNode){ atomicAdd(&g_SA[c], (double)st1); atomicAdd(&g_SA[64+c], (double)st2); }
    else if (isEdge){ atomicAdd(&g_SG[c], (double)st1); atomicAdd(&g_SG[41+c], (double)st2); }
}

__global__ void k_node_update()
{
    int idx = blockIdx.x*blockDim.x + threadIdx.x;
    if (idx >= N_ATOM*FDIM) return;
    int c = idx & 63;
    float v = g_NODE[idx] + (g_AGGR[idx] - g_MEANA[c]) * g_ISTDA[c];
    g_NODE[idx] = lrelu(v);
}

// ---------------- pass2 (head) ----------------
__global__ void __launch_bounds__(256) k_pass2_head(float* __restrict__ out)
{
    int warp = threadIdx.x >> 5, lane = threadIdx.x & 31;
    size_t r = (size_t)blockIdx.x*8 + warp;
    if (r >= N_ROW) return;
    float dist = g_DIST[r];
    float bd = 0.f, bc = 0.f;
    const float* y = g_Y + r*NC_H;
    #pragma unroll
    for (int i=0;i<8;i++){
        int cidx = lane + 32*i;
        float v = (y[cidx] - g_MEAN[cidx]) * g_ISTD[cidx];
        if (i < 4) bd += softplus(v + dist);
        else       bc += softplus(v);
    }
    #pragma unroll
    for (int o=16;o>0;o>>=1){
        bd += __shfl_down_sync(0xffffffffu, bd, o);
        bc += __shfl_down_sync(0xffffffffu, bc, o);
    }
    if (lane==0){
        out[r*2]   = bd * (1.f/128.f);
        out[r*2+1] = bc * (1.f/128.f) * (1.f/(float)N_ATOM);
    }
}

// ---------------- host orchestration ----------------
extern "C" void kernel_launch(void* const* d_in, const int* in_sizes, int n_in,
                              void* d_out, int out_size)
{
    const float* node_fea = (const float*)d_in[0];
    const float* edge_fea = (const float*)d_in[1];
    const float* nbr_off  = (const float*)d_in[2];
    const float* atom_pos = (const float*)d_in[3];
    const float* cells    = (const float*)d_in[4];
    const int*   eidx     = (const int*)  d_in[5];
    const float* W_emb = (const float*)d_in[6];
    const float* b_emb = (const float*)d_in[7];
    const float* W_pn  = (const float*)d_in[8];
    const float* b_pn  = (const float*)d_in[9];
    const float* W_pe  = (const float*)d_in[10];
    const float* b_pe  = (const float*)d_in[11];
    const float* W_d   = (const float*)d_in[12];
    const float* b_d   = (const float*)d_in[13];
    const float* W_c   = (const float*)d_in[14];
    const float* b_c   = (const float*)d_in[15];
    float* out = (float*)d_out;

    k_dist<<<(N_ROW+255)/256, 256>>>(nbr_off, atom_pos, cells, eidx);
    k_gemm_emb<<<(N_ATOM+63)/64, 256>>>(node_fea, W_emb, b_emb, N_ATOM, OFD, FDIM);

    for (int l=0;l<3;l++){
        k_pack_layer<<<64,256>>>(W_pn + (size_t)l*169*128, b_pn + l*128,
                                 W_pe + (size_t)l*169*82,  b_pe + l*82);
        k_gemm_uv<<<dim3((N_ATOM+127)/128, (UVS_L+127)/128), 256>>>(UVS_L);
        if (l == 0)
            k_pass1_l0<<<1216,256>>>(edge_fea, eidx);   // raw edge input
        else if (l == 1)
            k_pass1_l1<<<1216,256>>>(edge_fea, eidx);   // fuse update(edge_fea, G0) -> g_EDGE
        else
            k_pass1_l2<<<1216,256>>>(eidx);             // fuse update(g_EDGE, G1) -> g_EDGE
        k_finalize0<<<1,256>>>(NC_L, 1.0/(double)N_ROW);
        k_pass2_layer<<<2368,128>>>();
        k_finalize12<<<1,128>>>();
        k_node_update<<<(N_ATOM*FDIM+255)/256,256>>>();
    }

    k_pack_head<<<64,256>>>(W_d, b_d, W_c, b_c);
    k_gemm_uv<<<dim3((N_ATOM+127)/128, (UVS_H+127)/128), 256>>>(UVS_H);
    k_pass1_hd<<<1216,256>>>(eidx);                     // fuse update(g_EDGE, G2), no writeback
    k_finalize0<<<1,256>>>(NC_H, 1.0/(double)N_ROW);
    k_pass2_head<<<(int)((N_ROW+7)/8), 256>>>(out);
}

// round 6
// speedup vs baseline: 1.1931x; 1.1863x over previous
#include <cuda_runtime.h>
#include <math.h>

#define N_ATOM  50000
#define M_NBR   12
#define N_ROW   600000
#define OFD     92
#define FDIM    64
#define EDIMM   41
#define NC_L    210
#define NC_H    256
#define UVS_L   420
#define UVS_H   512

// ---------------- scratch (device globals; no runtime allocation) ----------------
__device__ __align__(16) float  g_Y[(size_t)N_ROW * NC_H];
__device__ __align__(16) float  g_G[(size_t)N_ROW * EDIMM];
__device__ __align__(16) float  g_EDGE[(size_t)N_ROW * EDIMM];
__device__ __align__(16) float  g_NODE[N_ATOM * FDIM];
__device__ __align__(16) float  g_AGGR[N_ATOM * FDIM];
__device__ __align__(16) float  g_UV[(size_t)N_ATOM * UVS_H];
__device__ __align__(16) float  g_WP[FDIM * UVS_H];
__device__ __align__(16) float  g_BP[UVS_H];
__device__ __align__(16) float  g_EW[EDIMM * NC_H];
__device__ __align__(16) float  g_DIST[N_ROW];
__device__ double g_S[2 * NC_H];
__device__ double g_SA[2 * FDIM];
__device__ double g_SG[2 * EDIMM];
__device__ float  g_MEAN[NC_H], g_ISTD[NC_H];
__device__ float  g_MEANA[FDIM], g_ISTDA[FDIM];
__device__ float  g_MEANG[EDIMM], g_ISTDG[EDIMM];

__device__ __forceinline__ float lrelu(float x){ return x > 0.f ? x : 0.01f*x; }
__device__ __forceinline__ float sigm(float x){ return 1.f/(1.f + __expf(-x)); }
__device__ __forceinline__ float softplus(float x){ return fmaxf(x,0.f) + log1pf(__expf(-fabsf(x))); }

// ---------------- packed f32x2 helpers (sm_103a FFMA2 via PTX) ----------------
__device__ __forceinline__ unsigned long long pack_dup(float x){
    unsigned long long r; unsigned int xi = __float_as_uint(x);
    asm("mov.b64 %0, {%1, %1};" : "=l"(r) : "r"(xi));
    return r;
}
__device__ __forceinline__ void fma2(unsigned long long &d, unsigned long long a, unsigned long long b){
    asm("fma.rn.f32x2 %0, %1, %2, %0;" : "+l"(d) : "l"(a), "l"(b));
}
__device__ __forceinline__ float2 unpack2(unsigned long long v){
    unsigned int lo, hi;
    asm("mov.b64 {%0, %1}, %2;" : "=r"(lo), "=r"(hi) : "l"(v));
    float2 f; f.x = __uint_as_float(lo); f.y = __uint_as_float(hi); return f;
}

// ---------------- distance ----------------
__global__ void k_dist(const float* __restrict__ nbr, const float* __restrict__ pos,
                       const float* __restrict__ cells, const int* __restrict__ eidx)
{
    int r = blockIdx.x*blockDim.x + threadIdx.x;
    if (r >= N_ROW) return;
    int n = r / M_NBR;
    float o0=nbr[r*3], o1=nbr[r*3+1], o2=nbr[r*3+2];
    const float* c = cells + (size_t)n*9;
    int g = eidx[r];
    float dd = 1e-12f;
    #pragma unroll
    for (int j=0;j<3;j++){
        float off = o0*c[j] + o1*c[3+j] + o2*c[6+j];
        float d = pos[g*3+j] + off - pos[n*3+j];
        dd += d*d;
    }
    g_DIST[r] = sqrtf(dd);
}

// ---------------- embedding GEMM: g_NODE = node_fea @ W_emb + b_emb ----------------
__global__ void __launch_bounds__(256) k_gemm_emb(const float* __restrict__ A,
                                                  const float* __restrict__ B,
                                                  const float* __restrict__ bias,
                                                  int Nrows, int K, int Ncols)
{
    __shared__ float As[64*32];
    __shared__ float Bs[32*128];
    int tid = threadIdx.x;
    int colT = tid & 31, rowT = tid >> 5;
    int r0 = blockIdx.x*64;
    float acc[8][4];
    #pragma unroll
    for (int ri=0;ri<8;ri++)
        #pragma unroll
        for (int ci=0;ci<4;ci++) acc[ri][ci]=0.f;

    for (int k0=0;k0<K;k0+=32){
        for (int i=tid;i<64*32;i+=256){
            int rr=i>>5, kk=i&31; int gr=r0+rr, gk=k0+kk;
            As[i] = (gr<Nrows && gk<K)? A[(size_t)gr*K+gk] : 0.f;
        }
        for (int i=tid;i<32*128;i+=256){
            int kk=i>>7, jj=i&127; int gk=k0+kk;
            Bs[i] = (gk<K && jj<Ncols)? B[(size_t)gk*Ncols+jj] : 0.f;
        }
        __syncthreads();
        #pragma unroll 4
        for (int kk=0;kk<32;kk++){
            float a[8];
            #pragma unroll
            for (int ri=0;ri<8;ri++) a[ri]=As[(rowT+8*ri)*32+kk];
            #pragma unroll
            for (int ci=0;ci<4;ci++){
                float b=Bs[kk*128 + colT + 32*ci];
                #pragma unroll
                for (int ri=0;ri<8;ri++) acc[ri][ci] = fmaf(a[ri], b, acc[ri][ci]);
            }
        }
        __syncthreads();
    }
    #pragma unroll
    for (int ri=0;ri<8;ri++){
        int gr=r0+rowT+8*ri;
        if (gr >= Nrows) continue;
        #pragma unroll
        for (int ci=0;ci<4;ci++){
            int gj=colT+32*ci;
            if (gj < Ncols) g_NODE[(size_t)gr*Ncols+gj] = acc[ri][ci] + bias[gj];
        }
    }
}

// ---------------- UV GEMM (f32x2): g_UV = g_NODE(50000x64) @ g_WP + g_BP ----------------
__global__ void __launch_bounds__(256) k_gemm_uv(int Ncols)
{
    __shared__ __align__(16) float As[16][128];   // [k][m]
    __shared__ __align__(16) float Bs[16][128];   // [k][n]
    int tid = threadIdx.x;
    int tx = tid & 15, ty = tid >> 4;
    int r0 = blockIdx.x*128, c0 = blockIdx.y*128;
    unsigned long long acc2[8][4];
    #pragma unroll
    for (int i=0;i<8;i++)
        #pragma unroll
        for (int p=0;p<4;p++) acc2[i][p]=0ull;

    for (int k0=0;k0<FDIM;k0+=16){
        #pragma unroll
        for (int h=0;h<2;h++){
            int arow = (tid>>2) + h*64;
            int acol = (tid&3)*4;
            float4 v = make_float4(0.f,0.f,0.f,0.f);
            int gr = r0 + arow;
            if (gr < N_ATOM) v = *(const float4*)&g_NODE[(size_t)gr*FDIM + k0 + acol];
            As[acol+0][arow]=v.x; As[acol+1][arow]=v.y; As[acol+2][arow]=v.z; As[acol+3][arow]=v.w;
        }
        #pragma unroll
        for (int h=0;h<2;h++){
            int brow = (tid>>5) + h*8;
            int bcol = (tid&31)*4;
            float4 v = make_float4(0.f,0.f,0.f,0.f);
            if (c0 + bcol < Ncols) v = *(const float4*)&g_WP[(size_t)(k0+brow)*Ncols + c0 + bcol];
            *(float4*)&Bs[brow][bcol] = v;
        }
        __syncthreads();
        #pragma unroll
        for (int kk=0;kk<16;kk++){
            float a[8];
            *(float4*)&a[0] = *(const float4*)&As[kk][ty*8];
            *(float4*)&a[4] = *(const float4*)&As[kk][ty*8+4];
            unsigned long long bp[4];
            #pragma unroll
            for (int p=0;p<4;p++) bp[p] = *(const unsigned long long*)&Bs[kk][tx*8 + 2*p];
            #pragma unroll
            for (int i=0;i<8;i++){
                unsigned long long ap = pack_dup(a[i]);
                #pragma unroll
                for (int p=0;p<4;p++) fma2(acc2[i][p], ap, bp[p]);
            }
        }
        __syncthreads();
    }
    #pragma unroll
    for (int ri=0;ri<8;ri++){
        int gr = r0 + ty*8 + ri;
        if (gr >= N_ATOM) continue;
        #pragma unroll
        for (int cj=0;cj<2;cj++){
            int gj = c0 + tx*8 + cj*4;
            if (gj < Ncols){
                float4 bv = *(const float4*)&g_BP[gj];
                float2 v0 = unpack2(acc2[ri][cj*2+0]);
                float2 v1 = unpack2(acc2[ri][cj*2+1]);
                float4 o;
                o.x = v0.x + bv.x;
                o.y = v0.y + bv.y;
                o.z = v1.x + bv.z;
                o.w = v1.y + bv.w;
                *(float4*)&g_UV[(size_t)gr*Ncols + gj] = o;
            }
        }
    }
}

// ---------------- weight packing (+ stat zeroing) ----------------
__global__ void k_pack_layer(const float* __restrict__ Wn, const float* __restrict__ bn,
                             const float* __restrict__ We, const float* __restrict__ be)
{
    int stride = gridDim.x*blockDim.x;
    int t0 = blockIdx.x*blockDim.x + threadIdx.x;
    for (int idx=t0; idx<FDIM*UVS_L; idx+=stride){
        int k = idx / UVS_L, j = idx % UVS_L;
        float v;
        if (j<128)       v = Wn[k*128 + j];
        else if (j<256)  v = Wn[(64+k)*128 + (j-128)];
        else if (j<338)  v = We[k*82 + (j-256)];
        else             v = We[(64+k)*82 + (j-338)];
        g_WP[idx] = v;
    }
    for (int j=t0;j<UVS_L;j+=stride){
        float v = 0.f;
        if (j<128) v = bn[j];
        else if (j>=256 && j<338) v = be[j-256];
        g_BP[j]=v;
    }
    for (int idx=t0;idx<EDIMM*NC_L;idx+=stride){
        int k=idx/NC_L, j=idx%NC_L;
        g_EW[idx] = (j<128)? Wn[(128+k)*128 + j] : We[(128+k)*82 + (j-128)];
    }
    if (t0 < 2*NC_H)  g_S[t0]=0.0;
    if (t0 < 2*FDIM)  g_SA[t0]=0.0;
    if (t0 < 2*EDIMM) g_SG[t0]=0.0;
}

__global__ void k_pack_head(const float* __restrict__ Wd, const float* __restrict__ bd,
                            const float* __restrict__ Wc, const float* __restrict__ bc)
{
    int stride = gridDim.x*blockDim.x;
    int t0 = blockIdx.x*blockDim.x + threadIdx.x;
    for (int idx=t0; idx<FDIM*UVS_H; idx+=stride){
        int k = idx / UVS_H, j = idx % UVS_H;
        float v;
        if (j<128)       v = Wd[k*128 + j];
        else if (j<256)  v = Wd[(64+k)*128 + (j-128)];
        else if (j<384)  v = Wc[k*128 + (j-256)];
        else             v = Wc[(64+k)*128 + (j-384)];
        g_WP[idx] = v;
    }
    for (int j=t0;j<UVS_H;j+=stride){
        float v = 0.f;
        if (j<128) v = bd[j];
        else if (j>=256 && j<384) v = bc[j-256];
        g_BP[j]=v;
    }
    for (int idx=t0;idx<EDIMM*NC_H;idx+=stride){
        int k=idx/NC_H, j=idx%NC_H;
        g_EW[idx] = (j<128)? Wd[(128+k)*128 + j] : Wc[(128+k)*128 + (j-128)];
    }
    if (t0 < 2*NC_H) g_S[t0]=0.0;
}

// ---------------- pass1 (f32x2): Y = edge@EW + U[n] + V[g]; channel stats ----------------
// Round-1 structure: 40-row tiles, 8 warps x 5 rows, scalar tile loads.
// Weights repacked in smem: per k, NPAIR pairs of columns (j, j+32) interleaved
// (one LDS.64 fetches both), plus optional scalar tail columns (NC=210: 18 valid).
template<int NC, int NPAIR, int HAS_SCALAR>
__global__ void __launch_bounds__(256,2) k_pass1(const float* __restrict__ Ein, int useG,
                                                 const int* __restrict__ eidx, int uvS)
{
    const int KSTRIDE = NPAIR*64 + (HAS_SCALAR?32:0);
    const int CPT     = 2*NPAIR + HAS_SCALAR;
    __shared__ __align__(16) float sEW[EDIMM*KSTRIDE];
    __shared__ __align__(16) float sE[40*EDIMM];
    const float* E = useG ? (const float*)g_EDGE : Ein;
    const int tid = threadIdx.x;
    const int colT = tid & 31, rowT = tid >> 5;

    for (int i=tid;i<EDIMM*KSTRIDE;i+=256) sEW[i]=0.f;
    __syncthreads();
    for (int i=tid;i<EDIMM*NC;i+=256){
        int k = i / NC, j = i - k*NC;
        float v = g_EW[i];
        int dest;
        if (HAS_SCALAR && j >= NPAIR*64)
            dest = k*KSTRIDE + NPAIR*64 + (j - NPAIR*64);
        else {
            int p = j>>6, c = j&63;
            dest = k*KSTRIDE + p*64 + ((c&31)<<1) + (c>>5);
        }
        sEW[dest] = v;
    }

    float s1[CPT], s2[CPT];
    #pragma unroll
    for (int ci=0;ci<CPT;ci++){ s1[ci]=0.f; s2[ci]=0.f; }

    const int nTiles = N_ROW / 40;
    for (int t = blockIdx.x; t < nTiles; t += gridDim.x){
        int r0 = t*40;
        __syncthreads();
        for (int i=tid;i<40*EDIMM;i+=256) sE[i] = E[(size_t)r0*EDIMM + i];
        __syncthreads();

        unsigned long long acc2[5][NPAIR];
        float acc1[5];
        #pragma unroll
        for (int ri=0;ri<5;ri++){
            acc1[ri]=0.f;
            #pragma unroll
            for (int p=0;p<NPAIR;p++) acc2[ri][p]=0ull;
        }
        const float* pE = sE + rowT*5*EDIMM;
        #pragma unroll 2
        for (int k=0;k<EDIMM;k++){
            float ev[5];
            unsigned long long evp[5];
            #pragma unroll
            for (int ri=0;ri<5;ri++){ ev[ri] = pE[ri*EDIMM + k]; evp[ri] = pack_dup(ev[ri]); }
            const float* wrow = sEW + k*KSTRIDE;
            unsigned long long wp[NPAIR];
            #pragma unroll
            for (int p=0;p<NPAIR;p++) wp[p] = *(const unsigned long long*)&wrow[p*64 + colT*2];
            #pragma unroll
            for (int p=0;p<NPAIR;p++)
                #pragma unroll
                for (int ri=0;ri<5;ri++) fma2(acc2[ri][p], evp[ri], wp[p]);
            if (HAS_SCALAR){
                float ws = wrow[NPAIR*64 + colT];
                #pragma unroll
                for (int ri=0;ri<5;ri++) acc1[ri] = fmaf(ev[ri], ws, acc1[ri]);
            }
        }
        #pragma unroll
        for (int ri=0;ri<5;ri++){
            int row = r0 + rowT*5 + ri;
            int n  = row / M_NBR;
            int gg = __ldg(&eidx[row]);
            const float* Un = g_UV + (size_t)n*uvS;
            const float* Vg = g_UV + (size_t)gg*uvS;
            float* yp = g_Y + (size_t)row*NC;
            #pragma unroll
            for (int p=0;p<NPAIR;p++){
                float2 y = unpack2(acc2[ri][p]);
                int j0 = colT + p*64, j1 = j0 + 32;
                int uc0 = (j0<128)? j0       : j0+128;
                int vc0 = (j0<128)? (j0+128) : j0+NC;
                int uc1 = (j1<128)? j1       : j1+128;
                int vc1 = (j1<128)? (j1+128) : j1+NC;
                float y0 = y.x + Un[uc0] + Vg[vc0];
                float y1 = y.y + Un[uc1] + Vg[vc1];
                yp[j0] = y0; yp[j1] = y1;
                s1[2*p]   += y0; s2[2*p]   += y0*y0;
                s1[2*p+1] += y1; s2[2*p+1] += y1*y1;
            }
            if (HAS_SCALAR && colT < (NC - NPAIR*64)){
                int j = NPAIR*64 + colT;
                float y = acc1[ri] + Un[j+128] + Vg[j+NC];
                yp[j] = y;
                s1[CPT-1] += y; s2[CPT-1] += y*y;
            }
        }
    }
    __syncthreads();
    float* red = sE;
    #pragma unroll 1
    for (int ci=0;ci<CPT;ci++){
        red[tid] = s1[ci];
        red[256+tid] = s2[ci];
        __syncthreads();
        if (tid < 32){
            float a=0.f, b=0.f;
            #pragma unroll
            for (int w=0;w<8;w++){ a += red[w*32+tid]; b += red[256+w*32+tid]; }
            int j = tid + 32*ci;
            if (j < NC){
                atomicAdd(&g_S[j],    (double)a);
                atomicAdd(&g_S[NC+j], (double)b);
            }
        }
        __syncthreads();
    }
}

// ---------------- finalize stats ----------------
__global__ void k_finalize0(int C, double invCnt)
{
    int t = threadIdx.x + blockIdx.x*blockDim.x;
    if (t >= C) return;
    double m = g_S[t]*invCnt;
    double v = g_S[C+t]*invCnt - m*m;
    g_MEAN[t] = (float)m;
    g_ISTD[t] = rsqrtf((float)v + 1e-5f);
}

__global__ void k_finalize12()
{
    int t = threadIdx.x;
    if (t < FDIM){
        double m = g_SA[t] * (1.0/(double)N_ATOM);
        double v = g_SA[FDIM+t] * (1.0/(double)N_ATOM) - m*m;
        g_MEANA[t] = (float)m;
        g_ISTDA[t] = rsqrtf((float)v + 1e-5f);
    } else if (t >= 64 && t < 64+EDIMM){
        int c = t-64;
        double m = g_SG[c] * (1.0/(double)N_ROW);
        double v = g_SG[EDIMM+c] * (1.0/(double)N_ROW) - m*m;
        g_MEANG[c] = (float)m;
        g_ISTDG[c] = rsqrtf((float)v + 1e-5f);
    }
}

// ---------------- pass2 (layer) ----------------
__global__ void __launch_bounds__(128) k_pass2_layer()
{
    int t = threadIdx.x;
    bool isNode = t < 64;
    bool isEdge = (t >= 64 && t < 105);
    float m1=0.f,i1=0.f,m2=0.f,i2=0.f;
    int c = 0;
    if (isNode){ c=t;    m1=g_MEAN[c];     i1=g_ISTD[c];     m2=g_MEAN[64+c];  i2=g_ISTD[64+c]; }
    else if (isEdge){ c=t-64; m1=g_MEAN[128+c]; i1=g_ISTD[128+c]; m2=g_MEAN[169+c]; i2=g_ISTD[169+c]; }
    float st1=0.f, st2=0.f;
    for (int n = blockIdx.x; n < N_ATOM; n += gridDim.x){
        if (isNode){
            float a = 0.f;
            #pragma unroll
            for (int m=0;m<M_NBR;m++){
                size_t row = (size_t)(n*M_NBR+m);
                float y1 = (g_Y[row*NC_L + c]      - m1)*i1;
                float y2 = (g_Y[row*NC_L + 64 + c] - m2)*i2;
                a += sigm(y1)*lrelu(y2);
            }
            g_AGGR[n*64 + c] = a;
            st1 += a; st2 += a*a;
        } else if (isEdge){
            #pragma unroll
            for (int m=0;m<M_NBR;m++){
                size_t row = (size_t)(n*M_NBR+m);
                float y1 = (g_Y[row*NC_L + 128 + c] - m1)*i1;
                float y2 = (g_Y[row*NC_L + 169 + c] - m2)*i2;
                float gv = sigm(y1)*lrelu(y2);
                g_G[row*EDIMM + c] = gv;
                st1 += gv; st2 += gv*gv;
            }
        }
    }
    if (isNode){ atomicAdd(&g_SA[c], (double)st1); atomicAdd(&g_SA[64+c], (double)st2); }
    else if (isEdge){ atomicAdd(&g_SG[c], (double)st1); atomicAdd(&g_SG[41+c], (double)st2); }
}

__global__ void k_node_update()
{
    int idx = blockIdx.x*blockDim.x + threadIdx.x;
    if (idx >= N_ATOM*FDIM) return;
    int c = idx & 63;
    float v = g_NODE[idx] + (g_AGGR[idx] - g_MEANA[c]) * g_ISTDA[c];
    g_NODE[idx] = lrelu(v);
}

__global__ void k_edge_update(const float* __restrict__ Ein, int useG)
{
    size_t idx = (size_t)blockIdx.x*blockDim.x + threadIdx.x;
    if (idx >= (size_t)N_ROW*EDIMM) return;
    int c = (int)(idx % EDIMM);
    float e = useG ? g_EDGE[idx] : Ein[idx];
    float v = e + (g_G[idx] - g_MEANG[c]) * g_ISTDG[c];
    g_EDGE[idx] = lrelu(v);
}

// ---------------- pass2 (head) ----------------
__global__ void __launch_bounds__(256) k_pass2_head(float* __restrict__ out)
{
    int warp = threadIdx.x >> 5, lane = threadIdx.x & 31;
    size_t r = (size_t)blockIdx.x*8 + warp;
    if (r >= N_ROW) return;
    float dist = g_DIST[r];
    float bd = 0.f, bc = 0.f;
    const float* y = g_Y + r*NC_H;
    #pragma unroll
    for (int i=0;i<8;i++){
        int cidx = lane + 32*i;
        float v = (y[cidx] - g_MEAN[cidx]) * g_ISTD[cidx];
        if (i < 4) bd += softplus(v + dist);
        else       bc += softplus(v);
    }
    #pragma unroll
    for (int o=16;o>0;o>>=1){
        bd += __shfl_down_sync(0xffffffffu, bd, o);
        bc += __shfl_down_sync(0xffffffffu, bc, o);
    }
    if (lane==0){
        out[r*2]   = bd * (1.f/128.f);
        out[r*2+1] = bc * (1.f/128.f) * (1.f/(float)N_ATOM);
    }
}

// ---------------- host orchestration ----------------
extern "C" void kernel_launch(void* const* d_in, const int* in_sizes, int n_in,
                              void* d_out, int out_size)
{
    const float* node_fea = (const float*)d_in[0];
    const float* edge_fea = (const float*)d_in[1];
    const float* nbr_off  = (const float*)d_in[2];
    const float* atom_pos = (const float*)d_in[3];
    const float* cells    = (const float*)d_in[4];
    const int*   eidx     = (const int*)  d_in[5];
    const float* W_emb = (const float*)d_in[6];
    const float* b_emb = (const float*)d_in[7];
    const float* W_pn  = (const float*)d_in[8];
    const float* b_pn  = (const float*)d_in[9];
    const float* W_pe  = (const float*)d_in[10];
    const float* b_pe  = (const float*)d_in[11];
    const float* W_d   = (const float*)d_in[12];
    const float* b_d   = (const float*)d_in[13];
    const float* W_c   = (const float*)d_in[14];
    const float* b_c   = (const float*)d_in[15];
    float* out = (float*)d_out;

    k_dist<<<(N_ROW+255)/256, 256>>>(nbr_off, atom_pos, cells, eidx);
    k_gemm_emb<<<(N_ATOM+63)/64, 256>>>(node_fea, W_emb, b_emb, N_ATOM, OFD, FDIM);

    for (int l=0;l<3;l++){
        int useG = (l>0) ? 1 : 0;
        k_pack_layer<<<64,256>>>(W_pn + (size_t)l*169*128, b_pn + l*128,
                                 W_pe + (size_t)l*169*82,  b_pe + l*82);
        k_gemm_uv<<<dim3((N_ATOM+127)/128, (UVS_L+127)/128), 256>>>(UVS_L);
        k_pass1<NC_L,3,1><<<1184,256>>>(edge_fea, useG, eidx, UVS_L);
        k_finalize0<<<1,256>>>(NC_L, 1.0/(double)N_ROW);
        k_pass2_layer<<<2368,128>>>();
        k_finalize12<<<1,128>>>();
        k_node_update<<<(N_ATOM*FDIM+255)/256,256>>>();
        k_edge_update<<<(int)(((size_t)N_ROW*EDIMM+255)/256),256>>>(edge_fea, useG);
    }

    k_pack_head<<<64,256>>>(W_d, b_d, W_c, b_c);
    k_gemm_uv<<<dim3((N_ATOM+127)/128, (UVS_H+127)/128), 256>>>(UVS_H);
    k_pass1<NC_H,4,0><<<1184,256>>>(edge_fea, 1, eidx, UVS_H);
    k_finalize0<<<1,256>>>(NC_H, 1.0/(double)N_ROW);
    k_pass2_head<<<(int)((N_ROW+7)/8), 256>>>(out);
}